// round 17
// baseline (speedup 1.0000x reference)
#include <cuda_runtime.h>

// ---------------- problem constants ----------------
#define NROWS     2048
#define RROWS     4          // batch rows per CTA (split 2+2 across thread row-halves)
#define NTHREADS  512
#define SPONGE_N  1024
#define HALFW     512
#define QUARTW    256
#define ACT_N     256
#define DEPTH_N   8
#define BDEPTH_N  10
#define BF_SIZE   3072
#define BF_HALF   1536
#define BF_QUART  768
#define BF_DEPTH  12

#define SP_STRIDE   4624                 // >= isp(1023)+4, 16B aligned
#define MEM_OFF     (2*SP_STRIDE)        // 9248
#define BF_STRIDE   13840                // >= ibf(3071)+4
#define SMEM_FLOATS (2*BF_STRIDE)        // 27680 floats = 110720 B -> 2 CTAs/SM

// ---------------- precomputed tables ----------------
__device__ __align__(16) float2 g_rot  [DEPTH_N*BDEPTH_N*HALFW];  // sponge (cos,sin)
__device__ __align__(16) float2 g_bfrot[BF_DEPTH*BF_HALF];        // final butterfly
__device__ float4 g_act  [DEPTH_N*ACT_N];           // (bias, c, t, 1/c)
__device__ int    g_recall[DEPTH_N*ACT_N];
__device__ int    g_outidx[2048];

__global__ void prep_kernel(const float* __restrict__ angles,
                            const float* __restrict__ bf_angles,
                            const float* __restrict__ act_bias,
                            const float* __restrict__ act_curv,
                            const void*  __restrict__ recall_raw,
                            const void*  __restrict__ out_raw)
{
    int i = blockIdx.x * blockDim.x + threadIdx.x;
    const int NROT = DEPTH_N*BDEPTH_N*HALFW;       // 40960
    const int NBF  = BF_DEPTH*BF_HALF;             // 18432
    if (i < NROT) {
        float s, c; __sincosf(__ldg(angles + i), &s, &c);
        g_rot[i] = make_float2(c, s);
    } else if (i < NROT + NBF) {
        int j = i - NROT;
        float s, c; __sincosf(__ldg(bf_angles + j), &s, &c);
        g_bfrot[j] = make_float2(c, s);
    } else if (i < NROT + NBF + DEPTH_N*ACT_N) {
        int k = i - NROT - NBF;
        float cu = __ldg(act_curv + k);
        float c  = 0.5f*(cu + sqrtf(cu*cu + 1.0f));
        g_act[k] = make_float4(__ldg(act_bias + k), c,
                               0.25f*3.14159265358979323846f/c, 1.0f/c);
    }
    // dtype-robust index decode (int32 vs int64)
    if (i < 2048) {
        const int* o32 = (const int*)out_raw;
        bool is64 = (o32[1]==0 && o32[3]==0 && o32[5]==0 && o32[7]==0);
        if (is64) {
            g_outidx[i] = (int)((const long long*)out_raw)[i];
            g_recall[i] = (int)((const long long*)recall_raw)[i];
        } else {
            g_outidx[i] = o32[i];
            g_recall[i] = ((const int*)recall_raw)[i];
        }
    }
}

// ---------------- padded shared-memory indexing ----------------
__device__ __forceinline__ int isp(int p) { return 4*p + ((p>>3)<<2) + ((p>>9)<<4); }
__device__ __forceinline__ int ibf(int p) { return 4*p + ((p>>3)<<2) + ((p>=1536)?16:0); }

// fixed offsets (verified constant across valid base positions)
#define SR1 576
#define SR2 1152
#define SR3 1728
#define SW1 4
#define SW2 2320       // isp(p+512)-isp(p)
#define SW3 2324
#define SSTEP 288      // isp(p+64)-isp(p), within half
#define BSTEP 864      // ibf(p+192)-ibf(p), within half
#define BWHI  6928     // ibf(p+1536)-ibf(p)

__device__ __forceinline__ float actf(float x, float c, float tt, float invc) {
    const float OOS2 = 0.70710678118654752f;
    float r = invc*(OOS2 - __cosf(0.78539816339744831f + c*x));
    if (x >  tt) r = invc*OOS2 + (x - tt);
    if (x < -tt) r = invc*(OOS2 - 1.0f);
    return r;
}

__device__ __forceinline__ float2 mix2(float c, float s, float2 a, float2 b) {
    return make_float2(c*a.x + s*b.x, c*a.y + s*b.y);
}

// in-place Givens rotation: float2 (2 rows) and scalar (1 row)
__device__ __forceinline__ void grot(float2& p, float2& r, float c, float s) {
    float2 pn = mix2(c,  s, p, r);
    float2 rn = mix2(c, -s, r, p);
    p = pn; r = rn;
}
__device__ __forceinline__ void grots(float& p, float& r, float c, float s) {
    float pn = c*p + s*r;
    float rn = c*r - s*p;
    p = pn; r = rn;
}

// coefficient prefetch for sponge fused-2 stage s5 of depth block rotd
__device__ __forceinline__ void pf_sp(const float2* __restrict__ rotd, int s5, int m,
                                      float2& c1, float2& c2, float4& c4)
{
    const float2* r0 = rotd + (2*s5)*HALFW;
    c1 = __ldg(r0 + m);
    c2 = __ldg(r0 + m + QUARTW);
    c4 = __ldg((const float4*)(rotd + (2*s5+1)*HALFW) + m);
}

// 3-layer fused butterfly, float2 rows (R15-proven; BF phase)
__device__ __forceinline__ void fused3(const float* __restrict__ IN,
                                       float* __restrict__ OUT,
                                       int rbs, int step, int wbs, int whi,
                                       const float2* a0, const float2* a1,
                                       const float2* a2, int g, int quart)
{
    float2 cA0 = __ldg(a0 + g);
    float2 cA1 = __ldg(a0 + g + quart);
    float2 cA2 = __ldg(a0 + g + 2*quart);
    float2 cA3 = __ldg(a0 + g + 3*quart);
    float4 cC  = __ldg((const float4*)a1 + g);
    float4 cD  = __ldg((const float4*)(a1 + 2*quart) + g);
    float4 cE  = __ldg((const float4*)a2 + 2*g);
    float4 cF  = __ldg((const float4*)a2 + 2*g + 1);

    float2 v0 = *(const float2*)(IN + rbs + 0*step);
    float2 v1 = *(const float2*)(IN + rbs + 1*step);
    float2 v2 = *(const float2*)(IN + rbs + 2*step);
    float2 v3 = *(const float2*)(IN + rbs + 3*step);
    float2 v4 = *(const float2*)(IN + rbs + 4*step);
    float2 v5 = *(const float2*)(IN + rbs + 5*step);
    float2 v6 = *(const float2*)(IN + rbs + 6*step);
    float2 v7 = *(const float2*)(IN + rbs + 7*step);

    grot(v0, v4, cA0.x, cA0.y);
    grot(v1, v5, cA1.x, cA1.y);
    grot(v2, v6, cA2.x, cA2.y);
    grot(v3, v7, cA3.x, cA3.y);
    grot(v0, v2, cC.x, cC.y);
    grot(v4, v6, cC.z, cC.w);
    grot(v1, v3, cD.x, cD.y);
    grot(v5, v7, cD.z, cD.w);
    grot(v0, v1, cE.x, cE.y);
    grot(v2, v3, cE.z, cE.w);
    grot(v4, v5, cF.x, cF.y);
    grot(v6, v7, cF.z, cF.w);

    *(float2*)(OUT + wbs +  0)       = v0;
    *(float2*)(OUT + wbs +  0 + whi) = v1;
    *(float2*)(OUT + wbs +  4)       = v2;
    *(float2*)(OUT + wbs +  4 + whi) = v3;
    *(float2*)(OUT + wbs +  8)       = v4;
    *(float2*)(OUT + wbs +  8 + whi) = v5;
    *(float2*)(OUT + wbs + 12)       = v6;
    *(float2*)(OUT + wbs + 12 + whi) = v7;
}

// 3-layer fused butterfly, SCALAR row (sponge; full 512-thread occupancy)
__device__ __forceinline__ void fused3s(const float* __restrict__ IN,
                                        float* __restrict__ OUT,
                                        int rbs, int step, int wbs, int whi,
                                        const float2* a0, const float2* a1,
                                        const float2* a2, int g, int quart)
{
    float2 cA0 = __ldg(a0 + g);
    float2 cA1 = __ldg(a0 + g + quart);
    float2 cA2 = __ldg(a0 + g + 2*quart);
    float2 cA3 = __ldg(a0 + g + 3*quart);
    float4 cC  = __ldg((const float4*)a1 + g);
    float4 cD  = __ldg((const float4*)(a1 + 2*quart) + g);
    float4 cE  = __ldg((const float4*)a2 + 2*g);
    float4 cF  = __ldg((const float4*)a2 + 2*g + 1);

    float v0 = IN[rbs + 0*step];
    float v1 = IN[rbs + 1*step];
    float v2 = IN[rbs + 2*step];
    float v3 = IN[rbs + 3*step];
    float v4 = IN[rbs + 4*step];
    float v5 = IN[rbs + 5*step];
    float v6 = IN[rbs + 6*step];
    float v7 = IN[rbs + 7*step];

    grots(v0, v4, cA0.x, cA0.y);
    grots(v1, v5, cA1.x, cA1.y);
    grots(v2, v6, cA2.x, cA2.y);
    grots(v3, v7, cA3.x, cA3.y);
    grots(v0, v2, cC.x, cC.y);
    grots(v4, v6, cC.z, cC.w);
    grots(v1, v3, cD.x, cD.y);
    grots(v5, v7, cD.z, cD.w);
    grots(v0, v1, cE.x, cE.y);
    grots(v2, v3, cE.z, cE.w);
    grots(v4, v5, cF.x, cF.y);
    grots(v6, v7, cF.z, cF.w);

    OUT[wbs +  0]       = v0;
    OUT[wbs +  0 + whi] = v1;
    OUT[wbs +  4]       = v2;
    OUT[wbs +  4 + whi] = v3;
    OUT[wbs +  8]       = v4;
    OUT[wbs +  8 + whi] = v5;
    OUT[wbs + 12]       = v6;
    OUT[wbs + 12 + whi] = v7;
}

__global__ void __launch_bounds__(NTHREADS, 2)
sponge_kernel(const float* __restrict__ X,
              const float* __restrict__ scales,
              float* __restrict__ out)
{
    extern __shared__ float sb[];
    const int t    = threadIdx.x;
    const int row0 = blockIdx.x * RROWS;
    float* const MEMB = sb + MEM_OFF;

    // ---- load X * scales into sponge buffer 0 ----
    {
        float sc0 = scales[t], sc1 = scales[t + HALFW];
        int i0 = isp(t), i1 = i0 + SW2;
        #pragma unroll
        for (int r = 0; r < RROWS; r++) {
            const float* xr = X + (size_t)(row0 + r) * SPONGE_N;
            sb[i0 + r] = xr[t]         * sc0;
            sb[i1 + r] = xr[t + HALFW] * sc1;
        }
    }

    // ---- per-thread constants: thread = (pair m, row-half rh) ----
    const int  m   = t >> 1;
    const int  rh  = t & 1;
    const bool odd = rh;
    const int  A1  = (m >> 1) + (m & 1) * HALFW;
    const int  rb  = isp(A1)  + 2*rh;
    const int  wb  = isp(2*m) + 2*rh;
    const int  w0  = isp(t);
    const int  w1  = w0 + SW2;
    const int  ja  = t >> 1;
    const int  qa  = (t >= QUARTW) ? (t - QUARTW) : 0;   // recall slot (valid t>=256)

    // sponge fused-3 SCALAR constants: unit gsc = t>>2 in [0,128), row r4 = t&3
    const int gsc   = t >> 2;
    const int r4    = t & 3;
    const int rbs3  = isp(gsc >> 1) + SW2*(gsc & 1) + r4;
    const int wbs3  = isp(4*gsc) + r4;

    float2 c1, c2; float4 c4;                    // fused-2 coeff pipeline
    float4 ap;  int mi = 0;

    __syncthreads();

    int cur = 0;
    for (int d = 0; d < DEPTH_N; d++) {
        const float2* rotd = g_rot + d*(BDEPTH_N*HALFW);

        // ---- two fused-3 stages (layers 0-2, 3-5); ALL 512 threads, scalar rows ----
        #pragma unroll
        for (int st = 0; st < 2; st++) {
            if (st == 1) pf_sp(rotd, 3, m, c1, c2, c4);   // prefetch f2-A (layers 6,7)
            const float2* a0 = rotd + (3*st)*HALFW;
            fused3s(sb + cur*SP_STRIDE, sb + (cur^1)*SP_STRIDE,
                    rbs3, SSTEP, wbs3, SW2,
                    a0, a0 + HALFW, a0 + 2*HALFW, gsc, 128);
            cur ^= 1;
            __syncthreads();
        }

        // ---- two fused-2 stages (layers 6-7, 8-9) with prefetch pipeline ----
        #pragma unroll
        for (int r2 = 0; r2 < 2; r2++) {
            float2 u1 = c1, u2 = c2; float4 u4 = c4;
            if (r2 == 0) {
                pf_sp(rotd, 4, m, c1, c2, c4);            // prefetch f2-B (layers 8,9)
            } else {
                ap = g_act[d*ACT_N + ja];
                mi = __ldg(g_recall + d*ACT_N + qa);
            }
            const float* IN  = sb + cur*SP_STRIDE;
            float*       OUT = sb + (cur^1)*SP_STRIDE;

            float2 a1 = *(const float2*)(IN + rb);
            float2 a2 = *(const float2*)(IN + rb + SR1);
            float2 b1 = *(const float2*)(IN + rb + SR2);
            float2 b2 = *(const float2*)(IN + rb + SR3);
            float2 y1e = mix2(u1.x,  u1.y, a1, b1);
            float2 y1o = mix2(u1.x, -u1.y, b1, a1);
            float2 y2e = mix2(u2.x,  u2.y, a2, b2);
            float2 y2o = mix2(u2.x, -u2.y, b2, a2);
            *(float2*)(OUT + wb)       = mix2(u4.x,  u4.y, y1e, y2e);
            *(float2*)(OUT + wb + SW1) = mix2(u4.z,  u4.w, y1o, y2o);
            *(float2*)(OUT + wb + SW2) = mix2(u4.x, -u4.y, y2e, y1e);
            *(float2*)(OUT + wb + SW3) = mix2(u4.z, -u4.w, y2o, y1o);
            cur ^= 1;
            __syncthreads();
        }

        // ---- activation / mem store / recall: ONE barrier (R9-proven) ----
        {
            const float* S    = sb + cur*SP_STRIDE;
            float*       OUTB = sb + (cur^1)*SP_STRIDE;

            float4 x  = *(const float4*)(S + isp(HALFW + ja));
            float sg  = odd ? -1.0f : 1.0f;
            float4 o;
            o.x = actf(sg*(x.x + ap.x), ap.y, ap.z, ap.w);
            o.y = actf(sg*(x.y + ap.x), ap.y, ap.z, ap.w);
            o.z = actf(sg*(x.z + ap.x), ap.y, ap.z, ap.w);
            o.w = actf(sg*(x.w + ap.x), ap.y, ap.z, ap.w);

            float4 mv = *(const float4*)(S + w0);
            *(float4*)(MEMB + (d*HALFW + t)*RROWS) = mv;

            *(float4*)(OUTB + w0) = o;                        // act_out -> [0,512)
            if (t < QUARTW) {
                float4 kv = *(const float4*)(S + isp(3*QUARTW + t));
                *(float4*)(OUTB + isp(HALFW + t)) = kv;       // [768,1024)->[512,768)
            } else {
                float4 rv = (mi >= d*HALFW)
                    ? *(const float4*)(S + isp(mi - d*HALFW))
                    : *(const float4*)(MEMB + mi*RROWS);
                *(float4*)(OUTB + isp(3*QUARTW + qa)) = rv;   // recall -> [768,1024)
            }
            cur ^= 1;
            __syncthreads();
        }
    }
    // 5 flips per depth x 8 = 40 -> cur = 0; sponge in buffer 0

    // ---- build pre = [mem[out_idx] (2048), sponge (1024)] in BF buffer 0 ----
    {
        float4 s0 = *(const float4*)(sb + w0);
        float4 s1 = *(const float4*)(sb + w1);
        int oi0 = g_outidx[t];
        int oi1 = g_outidx[t + NTHREADS];
        int oi2 = g_outidx[t + 2*NTHREADS];
        int oi3 = g_outidx[t + 3*NTHREADS];
        __syncthreads();
        *(float4*)(sb + ibf(t))              = *(const float4*)(MEMB + oi0*RROWS);
        *(float4*)(sb + ibf(t + NTHREADS))   = *(const float4*)(MEMB + oi1*RROWS);
        *(float4*)(sb + ibf(t + 2*NTHREADS)) = *(const float4*)(MEMB + oi2*RROWS);
        *(float4*)(sb + ibf(t + 3*NTHREADS)) = *(const float4*)(MEMB + oi3*RROWS);
        __syncthreads();
        *(float4*)(sb + ibf(2048 + t))         = s0;
        *(float4*)(sb + ibf(2048 + HALFW + t)) = s1;
        __syncthreads();
    }

    // ---- final 12-layer butterfly: 4 fused-3 stages (R15-proven) ----
    {
        int bcur = 0;
        for (int st = 0; st < 4; st++) {
            const float2* a0 = g_bfrot + (3*st+0)*BF_HALF;
            const float2* a1 = g_bfrot + (3*st+1)*BF_HALF;
            const float2* a2 = g_bfrot + (3*st+2)*BF_HALF;
            const float* IN  = sb + bcur*BF_STRIDE;
            float*       OUT = sb + (bcur^1)*BF_STRIDE;
            #pragma unroll
            for (int ps = 0; ps < 2; ps++) {
                if (ps == 0 || t < 256) {
                    int u = m + 256*ps;
                    int h = u >> 1, e = u & 1;
                    fused3(IN, OUT,
                           ibf(h) + BWHI*e + 2*rh, BSTEP,
                           ibf(4*u) + 2*rh, BWHI,
                           a0, a1, a2, u, 384);
                }
            }
            bcur ^= 1;
            __syncthreads();
        }
    }

    // result in buffer 0 (4 flips); emit first 512 columns
    {
        float4 v = *(const float4*)(sb + ibf(t));
        out[(size_t)(row0 + 0)*HALFW + t] = v.x;
        out[(size_t)(row0 + 1)*HALFW + t] = v.y;
        out[(size_t)(row0 + 2)*HALFW + t] = v.z;
        out[(size_t)(row0 + 3)*HALFW + t] = v.w;
    }
}

extern "C" void kernel_launch(void* const* d_in, const int* in_sizes, int n_in,
                              void* d_out, int out_size)
{
    (void)in_sizes; (void)n_in; (void)out_size;
    const float* X          = (const float*)d_in[0];
    const float* scales     = (const float*)d_in[1];
    const float* angles     = (const float*)d_in[2];
    const float* act_bias   = (const float*)d_in[3];
    // d_in[4] = act_activation (unused by reference)
    const float* act_curv   = (const float*)d_in[5];
    const float* bf_angles  = (const float*)d_in[6];
    // d_in[7] = shuffle_perm (deterministic riffle, computed inline)
    const void*  recall_raw = d_in[8];
    const void*  out_raw    = d_in[9];
    // d_in[10] = bf_perm (deterministic riffle, computed inline)
    float* out = (float*)d_out;

    const int totalPrep = DEPTH_N*BDEPTH_N*HALFW + BF_DEPTH*BF_HALF + DEPTH_N*ACT_N;
    prep_kernel<<<(totalPrep + 511)/512, 512>>>(angles, bf_angles, act_bias, act_curv,
                                                recall_raw, out_raw);

    size_t smem = SMEM_FLOATS * sizeof(float);
    cudaFuncSetAttribute(sponge_kernel, cudaFuncAttributeMaxDynamicSharedMemorySize, (int)smem);
    sponge_kernel<<<NROWS/RROWS, NTHREADS, smem>>>(X, scales, out);
}